// round 11
// baseline (speedup 1.0000x reference)
#include <cuda_runtime.h>
#include <cuda_bf16.h>
#include <cstdint>

// ===========================================================================
// PIGNN forward — mma.sync bf16 hi/lo split GEMMs, persistent-B in smem.
// R8 sync skeleton (2 barriers/slab, wait_group 1) + pass-major MMA bursts
// (8 independent MMAs per split pass) to break accumulator dependency chains.
//   msg_in @ mW == h[src]@mW1 + h[dst]@mW2 + e@mW3
//   upd == relu(h@uW1 + agg@uW2 + ub); agg pre-split by splitagg kernel.
// ===========================================================================

#define NN_MAX 100000
#define NE_MAX 600000

__device__ float g_h   [(size_t)NN_MAX * 128];
__device__ float g_agg [(size_t)NN_MAX * 128];
__device__ float g_f1  [(size_t)NN_MAX * 128];   // U1 during layers, f1 in decoder
__device__ float g_p1  [(size_t)NN_MAX * 128];
__device__ float g_p2  [(size_t)NN_MAX * 128];
__device__ __nv_bfloat16 g_hhi[(size_t)NN_MAX * 128];
__device__ __nv_bfloat16 g_hlo[(size_t)NN_MAX * 128];
__device__ __nv_bfloat16 g_ehi[(size_t)NE_MAX * 128];
__device__ __nv_bfloat16 g_elo[(size_t)NE_MAX * 128];
__device__ __nv_bfloat16 g_thi[(size_t)NE_MAX * 128];   // mlp1 out / agg-split
__device__ __nv_bfloat16 g_tlo[(size_t)NE_MAX * 128];
#define W128_CNT 21
#define WUPD_OFF (W128_CNT * 16384)
#define WTOT (WUPD_OFF + 6 * 32768)
__device__ __nv_bfloat16 g_whi[WTOT];
__device__ __nv_bfloat16 g_wlo[WTOT];
__device__ float g_zbias[128];   // zero-initialized, never written

// ---------------------------------------------------------------------------
__device__ __forceinline__ uint32_t smem_to_u32(const void* p) {
    uint32_t a;
    asm("{ .reg .u64 t; cvta.to.shared.u64 t, %1; cvt.u32.u64 %0, t; }" : "=r"(a) : "l"(p));
    return a;
}
__device__ __forceinline__ void ldmx4(uint32_t& r0, uint32_t& r1, uint32_t& r2, uint32_t& r3,
                                      uint32_t addr) {
    asm volatile("ldmatrix.sync.aligned.m8n8.x4.shared.b16 {%0,%1,%2,%3}, [%4];"
                 : "=r"(r0), "=r"(r1), "=r"(r2), "=r"(r3) : "r"(addr));
}
__device__ __forceinline__ void mma_bf16(float& c0, float& c1, float& c2, float& c3,
                                         uint32_t a0, uint32_t a1, uint32_t a2, uint32_t a3,
                                         uint32_t b0, uint32_t b1) {
    asm volatile("mma.sync.aligned.m16n8k16.row.col.f32.bf16.bf16.f32 "
                 "{%0,%1,%2,%3}, {%4,%5,%6,%7}, {%8,%9}, {%0,%1,%2,%3};"
                 : "+f"(c0), "+f"(c1), "+f"(c2), "+f"(c3)
                 : "r"(a0), "r"(a1), "r"(a2), "r"(a3), "r"(b0), "r"(b1));
}
__device__ __forceinline__ void cpa16(uint32_t saddr, const void* g) {
    asm volatile("cp.async.cg.shared.global [%0], [%1], 16;" :: "r"(saddr), "l"(g));
}
#define CP_COMMIT() asm volatile("cp.async.commit_group;" ::: "memory")
#define CP_WAIT1()  asm volatile("cp.async.wait_group 1;" ::: "memory")
#define CP_WAIT0()  asm volatile("cp.async.wait_group 0;" ::: "memory")
__device__ __forceinline__ void red_add_v2(float* addr, float a, float b) {
    asm volatile("red.global.add.v2.f32 [%0], {%1,%2};"
                 :: "l"(addr), "f"(a), "f"(b) : "memory");
}
__device__ __forceinline__ uint32_t pack_bf2(float a, float b) {
    __nv_bfloat162 v = __floats2bfloat162_rn(a, b);
    return *reinterpret_cast<uint32_t*>(&v);
}
__device__ __forceinline__ void split2(float a, float b, uint32_t& hp, uint32_t& lp) {
    __nv_bfloat16 ha = __float2bfloat16(a), hb = __float2bfloat16(b);
    float la = a - __bfloat162float(ha), lb = b - __bfloat162float(hb);
    __nv_bfloat162 hh = __nv_bfloat162(ha, hb);
    hp = *reinterpret_cast<uint32_t*>(&hh);
    lp = pack_bf2(la, lb);
}
__device__ __forceinline__ void split4(const float4 v, uint32_t& h01, uint32_t& h23,
                                       uint32_t& l01, uint32_t& l23) {
    split2(v.x, v.y, h01, l01);
    split2(v.z, v.w, h23, l23);
}

// ---------------------------------------------------------------------------
// SMEM: persistent B (hi 32K @0, lo 32K @32768; 4 slabs x 8K each) +
// 2 A stages @65536 (each: AHI 8K + ALO 8K = 16K). Total 96KB -> 2 CTAs/SM.
#define OFF_BLOP 32768
#define OFF_AST  65536
#define SMEM_BYTES (OFF_AST + 2 * 16384)
#define SWZ(row, chunk) ((uint32_t)(row) * 64 + ((uint32_t)((chunk) ^ (((row) >> 1) & 3)) << 4))

struct Seg { const __nv_bfloat16* bhi; const __nv_bfloat16* blo;
             const float* bias; float* cout; int ldb; };
struct Segs { Seg s[3]; };

// ---------------------------------------------------------------------------
// GEMM: tile 128x128, K=128 (4 slabs of 32), 3-pass bf16 split, 256 thr,
// persistent B, persistent CTAs, 2-stage A pipeline (R8 sync structure),
// pass-major MMA bursts.
// EPI: 0 store fp32 (RELU opt) | 1 store split | 3 msg RED | 4 fp32+split
//      5 upd2: o=relu(U1+acc+b); cout+=o; split cout
// NSEG: static CTA partition over up to 3 (B, bias, cout) segments.
template<int EPI, bool RELU, int NSEG>
__global__ __launch_bounds__(256, 2)
void gk(Segs segs,
        const __nv_bfloat16* __restrict__ Ahi, const __nv_bfloat16* __restrict__ Alo,
        __nv_bfloat16* __restrict__ OutHi, __nv_bfloat16* __restrict__ OutLo,
        const int* __restrict__ src, const int* __restrict__ dst,
        const float* __restrict__ P1, const float* __restrict__ P2,
        float* __restrict__ AGGZ, const float* __restrict__ U1,
        int M, int ntiles)
{
    extern __shared__ char smem[];
    const uint32_t sb = smem_to_u32(smem);
    const int t = threadIdx.x;
    const int lane = t & 31;
    const int wid = t >> 5;
    const int wm = wid & 3;
    const int wn = wid >> 2;

    const int seg  = (NSEG == 1) ? 0 : (blockIdx.x % NSEG);
    const int nbSeg = gridDim.x / NSEG;
    const int bidS = (NSEG == 1) ? blockIdx.x : (blockIdx.x / NSEG);
    const Seg sg = segs.s[seg];

    const int ntl = (bidS < ntiles) ? ((ntiles - 1 - bidS) / nbSeg + 1) : 0;
    const int L = ntl * 4;
    if (L == 0) return;

    const int c2 = (lane & 3) * 2;
    float2 bw[8];
#pragma unroll
    for (int jn = 0; jn < 8; ++jn)
        bw[jn] = *reinterpret_cast<const float2*>(&sg.bias[wn * 64 + jn * 8 + c2]);

    // ---- persistent B load (4 slabs, hi+lo) ----
#pragma unroll
    for (int i = 0; i < 8; ++i) {
        int id = t + i * 256;            // 0..2047
        int slab = id >> 9;
        int row = (id >> 2) & 127;
        int c = id & 3;
        uint32_t off = (uint32_t)slab * 8192 + SWZ(row, c);
        size_t gix = (size_t)row * sg.ldb + slab * 32 + c * 8;
        cpa16(sb + off, sg.bhi + gix);
        cpa16(sb + OFF_BLOP + off, sg.blo + gix);
    }
    CP_COMMIT();

    auto fillA = [&](int l) {
        int tl = l >> 2;
        int s = l & 3;
        int m0f = (bidS + tl * nbSeg) * 128;
        int kb = s << 5;
        uint32_t buf = sb + OFF_AST + (uint32_t)(l & 1) * 16384;
#pragma unroll
        for (int i = 0; i < 2; ++i) {
            int id = t + i * 256;
            int row = id >> 2;
            int c = id & 3;
            int m = m0f + row;
            int mc = m < M ? m : M - 1;
            uint32_t off = SWZ(row, c);
            cpa16(buf + off, Ahi + (size_t)mc * 128 + kb + c * 8);
            cpa16(buf + 8192 + off, Alo + (size_t)mc * 128 + kb + c * 8);
        }
        CP_COMMIT();
    };

    fillA(0);

    float acc[2][8][4];
#pragma unroll
    for (int i = 0; i < 2; ++i)
#pragma unroll
        for (int j = 0; j < 8; ++j)
#pragma unroll
            for (int r = 0; r < 4; ++r) acc[i][j][r] = 0.f;

    int tl_cur = 0;
    for (int l = 0; l < L; ++l) {
        __syncthreads();                       // prior readers of next stage done
        if (l + 1 < L) { fillA(l + 1); CP_WAIT1(); }
        else CP_WAIT0();
        __syncthreads();                       // fills visible
        const uint32_t bufA = sb + OFF_AST + (uint32_t)(l & 1) * 16384;
        const uint32_t bufB = sb + (uint32_t)(l & 3) * 8192;
#pragma unroll
        for (int ks = 0; ks < 2; ++ks) {
            uint32_t ahi[2][4], alo[2][4];
            uint32_t ca = ks * 2 + (lane >> 4);
            uint32_t arow = wm * 32 + (lane & 15);
#pragma unroll
            for (int i = 0; i < 2; ++i) {
                uint32_t r = arow + i * 16;
                uint32_t off = SWZ(r, ca);
                ldmx4(ahi[i][0], ahi[i][1], ahi[i][2], ahi[i][3], bufA + off);
                ldmx4(alo[i][0], alo[i][1], alo[i][2], alo[i][3], bufA + 8192 + off);
            }
            uint32_t nr = wn * 64 + (lane & 7) + (lane >> 4) * 8;
            uint32_t cbk = ks * 2 + ((lane >> 3) & 1);
#pragma unroll
            for (int j2p = 0; j2p < 2; ++j2p) {
                uint32_t bh[2][4], bl[2][4];
#pragma unroll
                for (int jl = 0; jl < 2; ++jl) {
                    uint32_t r = nr + (j2p * 2 + jl) * 16;
                    uint32_t off = SWZ(r, cbk);
                    ldmx4(bh[jl][0], bh[jl][1], bh[jl][2], bh[jl][3], bufB + off);
                    ldmx4(bl[jl][0], bl[jl][1], bl[jl][2], bl[jl][3],
                          bufB + OFF_BLOP + off);
                }
                // pass 1: hi*hi — 8 independent MMAs
#pragma unroll
                for (int jl = 0; jl < 2; ++jl)
#pragma unroll
                    for (int i = 0; i < 2; ++i)
#pragma unroll
                        for (int jj = 0; jj < 2; ++jj) {
                            float* c = acc[i][(j2p * 2 + jl) * 2 + jj];
                            mma_bf16(c[0], c[1], c[2], c[3],
                                     ahi[i][0], ahi[i][1], ahi[i][2], ahi[i][3],
                                     bh[jl][jj * 2], bh[jl][jj * 2 + 1]);
                        }
                // pass 2: lo*hi
#pragma unroll
                for (int jl = 0; jl < 2; ++jl)
#pragma unroll
                    for (int i = 0; i < 2; ++i)
#pragma unroll
                        for (int jj = 0; jj < 2; ++jj) {
                            float* c = acc[i][(j2p * 2 + jl) * 2 + jj];
                            mma_bf16(c[0], c[1], c[2], c[3],
                                     alo[i][0], alo[i][1], alo[i][2], alo[i][3],
                                     bh[jl][jj * 2], bh[jl][jj * 2 + 1]);
                        }
                // pass 3: hi*lo
#pragma unroll
                for (int jl = 0; jl < 2; ++jl)
#pragma unroll
                    for (int i = 0; i < 2; ++i)
#pragma unroll
                        for (int jj = 0; jj < 2; ++jj) {
                            float* c = acc[i][(j2p * 2 + jl) * 2 + jj];
                            mma_bf16(c[0], c[1], c[2], c[3],
                                     ahi[i][0], ahi[i][1], ahi[i][2], ahi[i][3],
                                     bl[jl][jj * 2], bl[jl][jj * 2 + 1]);
                        }
            }
        }

        if ((l & 3) == 3) {
            // ---- register-direct epilogue for tile tl_cur ----
            const int m0 = (bidS + tl_cur * nbSeg) * 128;
            ++tl_cur;
            float* co = sg.cout;
#pragma unroll
            for (int i = 0; i < 2; ++i) {
                const int ra = m0 + wm * 32 + i * 16 + (lane >> 2);
                const int rb = ra + 8;
                const bool va = ra < M, vb = rb < M;
                int sA = 0, dA = 0, sB = 0, dB = 0;
                if (EPI == 3) {
                    if (va) { sA = __ldg(&src[ra]); dA = __ldg(&dst[ra]); }
                    if (vb) { sB = __ldg(&src[rb]); dB = __ldg(&dst[rb]); }
                }
#pragma unroll
                for (int jn = 0; jn < 8; ++jn) {
                    float* c = acc[i][jn];
                    const int col = wn * 64 + jn * 8 + c2;
                    float v0 = c[0] + bw[jn].x, v1 = c[1] + bw[jn].y;
                    float v2 = c[2] + bw[jn].x, v3 = c[3] + bw[jn].y;
                    c[0] = c[1] = c[2] = c[3] = 0.f;
                    if (EPI == 0 || EPI == 4) {
                        if (RELU) { v0 = fmaxf(v0, 0.f); v1 = fmaxf(v1, 0.f);
                                    v2 = fmaxf(v2, 0.f); v3 = fmaxf(v3, 0.f); }
                        if (va) *reinterpret_cast<float2*>(&co[(size_t)ra * 128 + col]) =
                            make_float2(v0, v1);
                        if (vb) *reinterpret_cast<float2*>(&co[(size_t)rb * 128 + col]) =
                            make_float2(v2, v3);
                        if (EPI == 4) {
                            uint32_t hp, lp;
                            if (va) {
                                split2(v0, v1, hp, lp);
                                *reinterpret_cast<uint32_t*>(OutHi + (size_t)ra * 128 + col) = hp;
                                *reinterpret_cast<uint32_t*>(OutLo + (size_t)ra * 128 + col) = lp;
                            }
                            if (vb) {
                                split2(v2, v3, hp, lp);
                                *reinterpret_cast<uint32_t*>(OutHi + (size_t)rb * 128 + col) = hp;
                                *reinterpret_cast<uint32_t*>(OutLo + (size_t)rb * 128 + col) = lp;
                            }
                        }
                    } else if (EPI == 1) {
                        uint32_t hp, lp;
                        if (va) {
                            split2(v0, v1, hp, lp);
                            *reinterpret_cast<uint32_t*>(OutHi + (size_t)ra * 128 + col) = hp;
                            *reinterpret_cast<uint32_t*>(OutLo + (size_t)ra * 128 + col) = lp;
                        }
                        if (vb) {
                            split2(v2, v3, hp, lp);
                            *reinterpret_cast<uint32_t*>(OutHi + (size_t)rb * 128 + col) = hp;
                            *reinterpret_cast<uint32_t*>(OutLo + (size_t)rb * 128 + col) = lp;
                        }
                    } else if (EPI == 5) {
                        uint32_t hp, lp;
                        if (va) {
                            float2 u = __ldg(reinterpret_cast<const float2*>(
                                                 &U1[(size_t)ra * 128 + col]));
                            float2 o = *reinterpret_cast<float2*>(&co[(size_t)ra * 128 + col]);
                            o.x += fmaxf(v0 + u.x, 0.f);
                            o.y += fmaxf(v1 + u.y, 0.f);
                            *reinterpret_cast<float2*>(&co[(size_t)ra * 128 + col]) = o;
                            split2(o.x, o.y, hp, lp);
                            *reinterpret_cast<uint32_t*>(OutHi + (size_t)ra * 128 + col) = hp;
                            *reinterpret_cast<uint32_t*>(OutLo + (size_t)ra * 128 + col) = lp;
                        }
                        if (vb) {
                            float2 u = __ldg(reinterpret_cast<const float2*>(
                                                 &U1[(size_t)rb * 128 + col]));
                            float2 o = *reinterpret_cast<float2*>(&co[(size_t)rb * 128 + col]);
                            o.x += fmaxf(v2 + u.x, 0.f);
                            o.y += fmaxf(v3 + u.y, 0.f);
                            *reinterpret_cast<float2*>(&co[(size_t)rb * 128 + col]) = o;
                            split2(o.x, o.y, hp, lp);
                            *reinterpret_cast<uint32_t*>(OutHi + (size_t)rb * 128 + col) = hp;
                            *reinterpret_cast<uint32_t*>(OutLo + (size_t)rb * 128 + col) = lp;
                        }
                    } else {  // EPI 3
                        if (va) {
                            float2 a1 = __ldg(reinterpret_cast<const float2*>(
                                                  &P1[(size_t)sA * 128 + col]));
                            float2 a2 = __ldg(reinterpret_cast<const float2*>(
                                                  &P2[(size_t)dA * 128 + col]));
                            float x0 = fmaxf(v0 + a1.x + a2.x, 0.f);
                            float x1 = fmaxf(v1 + a1.y + a2.y, 0.f);
                            red_add_v2(&AGGZ[(size_t)dA * 128 + col], x0, x1);
                        }
                        if (vb) {
                            float2 a1 = __ldg(reinterpret_cast<const float2*>(
                                                  &P1[(size_t)sB * 128 + col]));
                            float2 a2 = __ldg(reinterpret_cast<const float2*>(
                                                  &P2[(size_t)dB * 128 + col]));
                            float x2 = fmaxf(v2 + a1.x + a2.x, 0.f);
                            float x3 = fmaxf(v3 + a1.y + a2.y, 0.f);
                            red_add_v2(&AGGZ[(size_t)dB * 128 + col], x2, x3);
                        }
                    }
                }
            }
        }
    }
}

// ---------------------------------------------------------------------------
// split agg (fp32) -> bf16 hi/lo, and zero agg for the next layer
__global__ void splitagg(float* __restrict__ agg, __nv_bfloat16* __restrict__ hi,
                         __nv_bfloat16* __restrict__ lo, int n4) {
    int i = blockIdx.x * blockDim.x + threadIdx.x;
    if (i >= n4) return;
    float4 v = reinterpret_cast<float4*>(agg)[i];
    uint32_t h01, h23, l01, l23;
    split4(v, h01, h23, l01, l23);
    reinterpret_cast<uint2*>(hi)[i] = make_uint2(h01, h23);
    reinterpret_cast<uint2*>(lo)[i] = make_uint2(l01, l23);
    reinterpret_cast<float4*>(agg)[i] = make_float4(0.f, 0.f, 0.f, 0.f);
}

// ---------------------------------------------------------------------------
struct PtrTab { const float* p[W128_CNT]; };

__global__ void prep_w128(PtrTab tab, __nv_bfloat16* __restrict__ hi, __nv_bfloat16* __restrict__ lo) {
    int mat = blockIdx.y;
    int i = blockIdx.x * 256 + threadIdx.x;
    if (i >= 16384) return;
    int n = i >> 7, k = i & 127;
    float w = tab.p[mat][k * 128 + n];
    __nv_bfloat16 h = __float2bfloat16(w);
    hi[(size_t)mat * 16384 + i] = h;
    lo[(size_t)mat * 16384 + i] = __float2bfloat16(w - __bfloat162float(h));
}
__global__ void prep_w256(const float* __restrict__ W, __nv_bfloat16* __restrict__ hi,
                          __nv_bfloat16* __restrict__ lo) {
    int mat = blockIdx.y;
    int i = blockIdx.x * 256 + threadIdx.x;
    if (i >= 32768) return;
    int n = i >> 8, k = i & 255;
    float w = W[(size_t)mat * 256 * 128 + k * 128 + n];
    __nv_bfloat16 h = __float2bfloat16(w);
    hi[(size_t)(WUPD_OFF + mat * 32768) + i] = h;
    lo[(size_t)(WUPD_OFF + mat * 32768) + i] = __float2bfloat16(w - __bfloat162float(h));
}

__global__ void zero_kernel(float* __restrict__ p, int n4) {
    int i = blockIdx.x * blockDim.x + threadIdx.x;
    if (i < n4) reinterpret_cast<float4*>(p)[i] = make_float4(0.f, 0.f, 0.f, 0.f);
}

// batched tiny-K first linear + relu, writes pre-split bf16 hi/lo
__global__ void mlp1_kernel(const float* __restrict__ X, const float* __restrict__ W,
                            const float* __restrict__ b,
                            __nv_bfloat16* __restrict__ outHi, __nv_bfloat16* __restrict__ outLo,
                            int K, int M)
{
    __shared__ float Ws[10 * 128];
    __shared__ float Xs[32 * 10];
    __shared__ float bs[128];
    int t = threadIdx.x;  // 128
    for (int i = t; i < K * 128; i += 128) Ws[i] = W[i];
    bs[t] = b[t];
    int r0 = blockIdx.x * 32;
    int nrow = min(32, M - r0);
    for (int i = t; i < nrow * K; i += 128) Xs[i] = X[(size_t)r0 * K + i];
    __syncthreads();
    for (int r = 0; r < nrow; ++r) {
        float acc = bs[t];
        for (int k = 0; k < K; ++k) acc += Xs[r * K + k] * Ws[k * 128 + t];
        acc = fmaxf(acc, 0.f);
        __nv_bfloat16 hv = __float2bfloat16(acc);
        outHi[(size_t)(r0 + r) * 128 + t] = hv;
        outLo[(size_t)(r0 + r) * 128 + t] = __float2bfloat16(acc - __bfloat162float(hv));
    }
}

// fused decoder tail
__global__ void dec2_kernel(const float* __restrict__ f1, const float* __restrict__ W2,
                            const float* __restrict__ b2, const float* __restrict__ W3,
                            const float* __restrict__ b3, const float* __restrict__ bc_disp,
                            const float* __restrict__ bc_rot, const float* __restrict__ face_mask,
                            float* __restrict__ out, int N)
{
    __shared__ float W2s[128 * 64];
    __shared__ float W3s[64 * 15];
    __shared__ float b2s[64], b3s[16];
    __shared__ float f1s[2][128];
    __shared__ float f2s[2][64];

    int t = threadIdx.x;
    for (int i = t; i < 128 * 64; i += 128) W2s[i] = W2[i];
    for (int i = t; i < 64 * 15;  i += 128) W3s[i] = W3[i];
    if (t < 64) b2s[t] = b2[t];
    if (t < 15) b3s[t] = b3[t];
    __syncthreads();

    int base = blockIdx.x * 64;
    for (int it = 0; it < 32; ++it) {
        int n0 = base + it * 2;
#pragma unroll
        for (int r = 0; r < 2; ++r) {
            int n = n0 + r;
            f1s[r][t] = (n < N) ? f1[(size_t)n * 128 + t] : 0.f;
        }
        __syncthreads();
        {
            int rn = t >> 6, j = t & 63;
            float acc = b2s[j];
#pragma unroll 8
            for (int k = 0; k < 128; ++k) acc += f1s[rn][k] * W2s[k * 64 + j];
            f2s[rn][j] = fmaxf(acc, 0.f);
        }
        __syncthreads();
        if (t < 30) {
            int rr = t / 15, c = t % 15;
            int n = n0 + rr;
            if (n < N) {
                float acc = b3s[c];
#pragma unroll 8
                for (int k = 0; k < 64; ++k) acc += f2s[rr][k] * W3s[k * 15 + c];
                float mask;
                if (c < 2)       mask = 1.f - bc_disp[n];
                else if (c == 2) mask = 1.f - bc_rot[n];
                else             mask = face_mask[(size_t)n * 4 + (c - 3) / 3];
                out[(size_t)n * 15 + c] = acc * mask;
            }
        }
        __syncthreads();
    }
}

// ---------------------------------------------------------------------------
extern "C" void kernel_launch(void* const* d_in, const int* in_sizes, int n_in,
                              void* d_out, int out_size)
{
    const float* x         = (const float*)d_in[0];
    const float* edge_attr = (const float*)d_in[1];
    const int*   edge_idx  = (const int*)  d_in[2];
    const float* bc_disp   = (const float*)d_in[3];
    const float* bc_rot    = (const float*)d_in[4];
    const float* face_mask = (const float*)d_in[5];
    const float* enc_n_W1  = (const float*)d_in[6];
    const float* enc_n_b1  = (const float*)d_in[7];
    const float* enc_n_W2  = (const float*)d_in[8];
    const float* enc_n_b2  = (const float*)d_in[9];
    const float* enc_e_W1  = (const float*)d_in[10];
    const float* enc_e_b1  = (const float*)d_in[11];
    const float* enc_e_W2  = (const float*)d_in[12];
    const float* enc_e_b2  = (const float*)d_in[13];
    const float* msg_W     = (const float*)d_in[14];
    const float* msg_b     = (const float*)d_in[15];
    const float* upd_W     = (const float*)d_in[16];
    const float* upd_b     = (const float*)d_in[17];
    const float* dec_W1    = (const float*)d_in[18];
    const float* dec_b1    = (const float*)d_in[19];
    const float* dec_W2    = (const float*)d_in[20];
    const float* dec_b2    = (const float*)d_in[21];
    const float* dec_W3    = (const float*)d_in[22];
    const float* dec_b3    = (const float*)d_in[23];

    const int N = in_sizes[0] / 9;
    const int E = in_sizes[1] / 10;
    const int* src = edge_idx;
    const int* dst = edge_idx + E;

    float *h, *agg, *f1, *p1, *p2, *zb;
    __nv_bfloat16 *hhi, *hlo, *ehi, *elo, *thi, *tlo, *whi, *wlo;
    cudaGetSymbolAddress((void**)&h,   g_h);
    cudaGetSymbolAddress((void**)&agg, g_agg);
    cudaGetSymbolAddress((void**)&f1,  g_f1);
    cudaGetSymbolAddress((void**)&p1,  g_p1);
    cudaGetSymbolAddress((void**)&p2,  g_p2);
    cudaGetSymbolAddress((void**)&zb,  g_zbias);
    cudaGetSymbolAddress((void**)&hhi, g_hhi);
    cudaGetSymbolAddress((void**)&hlo, g_hlo);
    cudaGetSymbolAddress((void**)&ehi, g_ehi);
    cudaGetSymbolAddress((void**)&elo, g_elo);
    cudaGetSymbolAddress((void**)&thi, g_thi);
    cudaGetSymbolAddress((void**)&tlo, g_tlo);
    cudaGetSymbolAddress((void**)&whi, g_whi);
    cudaGetSymbolAddress((void**)&wlo, g_wlo);

    cudaFuncSetAttribute((const void*)gk<0,false,3>, cudaFuncAttributeMaxDynamicSharedMemorySize, SMEM_BYTES);
    cudaFuncSetAttribute((const void*)gk<3,true,1>,  cudaFuncAttributeMaxDynamicSharedMemorySize, SMEM_BYTES);
    cudaFuncSetAttribute((const void*)gk<5,true,1>,  cudaFuncAttributeMaxDynamicSharedMemorySize, SMEM_BYTES);
    cudaFuncSetAttribute((const void*)gk<4,false,1>, cudaFuncAttributeMaxDynamicSharedMemorySize, SMEM_BYTES);
    cudaFuncSetAttribute((const void*)gk<1,false,1>, cudaFuncAttributeMaxDynamicSharedMemorySize, SMEM_BYTES);
    cudaFuncSetAttribute((const void*)gk<0,true,1>,  cudaFuncAttributeMaxDynamicSharedMemorySize, SMEM_BYTES);

    // ---- weight prep ----
    PtrTab tab;
    tab.p[0] = enc_n_W2;
    tab.p[1] = enc_e_W2;
    tab.p[2] = dec_W1;
    for (int l = 0; l < 6; ++l)
        for (int j = 0; j < 3; ++j)
            tab.p[3 + l * 3 + j] = msg_W + (size_t)l * 384 * 128 + (size_t)j * 128 * 128;
    prep_w128<<<dim3(64, W128_CNT), 256>>>(tab, whi, wlo);
    prep_w256<<<dim3(128, 6), 256>>>(upd_W, whi, wlo);

    const int gN = (N + 127) / 128;
    const int gE = (E + 127) / 128;
    auto WH = [&](int j) { return whi + (size_t)j * 16384; };
    auto WL = [&](int j) { return wlo + (size_t)j * 16384; };
    auto mkseg = [](const __nv_bfloat16* bh, const __nv_bfloat16* bl,
                    const float* bi, float* co, int ldb) {
        Seg s; s.bhi = bh; s.blo = bl; s.bias = bi; s.cout = co; s.ldb = ldb; return s;
    };

    const int PG1 = 296;                   // NSEG=1 grid
    const int PG3 = 294;                   // NSEG=3 grid (divisible by 3)
    auto g1 = [&](int nt) { return nt < PG1 ? nt : PG1; };

    // ---- encoders ----
    mlp1_kernel<<<(N + 31) / 32, 128>>>(x, enc_n_W1, enc_n_b1, thi, tlo, 9, N);
    {
        Segs sg; sg.s[0] = mkseg(WH(0), WL(0), enc_n_b2, h, 128);
        gk<4,false,1><<<g1(gN), 256, SMEM_BYTES>>>(sg, thi, tlo, hhi, hlo,
            nullptr, nullptr, nullptr, nullptr, nullptr, nullptr, N, gN);
    }
    mlp1_kernel<<<(E + 31) / 32, 128>>>(edge_attr, enc_e_W1, enc_e_b1, thi, tlo, 10, E);
    {
        Segs sg; sg.s[0] = mkseg(WH(1), WL(1), enc_e_b2, nullptr, 128);
        gk<1,false,1><<<g1(gE), 256, SMEM_BYTES>>>(sg, thi, tlo, ehi, elo,
            nullptr, nullptr, nullptr, nullptr, nullptr, nullptr, E, gE);
    }

    zero_kernel<<<(N * 128 / 4 + 255) / 256, 256>>>(agg, N * 128 / 4);

    // ---- message-passing layers ----
    for (int l = 0; l < 6; ++l) {
        int j = 3 + l * 3;
        const __nv_bfloat16* uh = whi + WUPD_OFF + (size_t)l * 32768;
        const __nv_bfloat16* ul = wlo + WUPD_OFF + (size_t)l * 32768;
        {   // P1 = h@mW1, P2 = h@mW2, U1 = h@uW1 (3 segments)
            Segs sg;
            sg.s[0] = mkseg(WH(j),   WL(j),   zb, p1, 128);
            sg.s[1] = mkseg(WH(j+1), WL(j+1), zb, p2, 128);
            sg.s[2] = mkseg(uh, ul, zb, f1, 256);
            int grid = (3 * gN < PG3) ? 3 * gN : PG3;
            gk<0,false,3><<<grid, 256, SMEM_BYTES>>>(sg, hhi, hlo, nullptr, nullptr,
                nullptr, nullptr, nullptr, nullptr, nullptr, nullptr, N, gN);
        }
        {   // msg: acc=e@mW3; epi relu(acc+b+P1[src]+P2[dst]) RED->agg[dst]
            Segs sg; sg.s[0] = mkseg(WH(j+2), WL(j+2), msg_b + l * 128, nullptr, 128);
            gk<3,true,1><<<g1(gE), 256, SMEM_BYTES>>>(sg, ehi, elo, nullptr, nullptr,
                src, dst, p1, p2, agg, nullptr, E, gE);
        }
        // agg -> bf16 hi/lo (thi/tlo), zero agg
        splitagg<<<(N * 32 + 255) / 256, 256>>>(agg, thi, tlo, N * 32);
        {   // upd2: o = relu(U1 + agg@uW2 + ub); h += o; split h
            Segs sg; sg.s[0] = mkseg(uh + 128, ul + 128, upd_b + l * 128, h, 256);
            gk<5,true,1><<<g1(gN), 256, SMEM_BYTES>>>(sg, thi, tlo, hhi, hlo,
                nullptr, nullptr, nullptr, nullptr, nullptr, f1, N, gN);
        }
    }

    // ---- decoder ----
    {
        Segs sg; sg.s[0] = mkseg(WH(2), WL(2), dec_b1, f1, 128);
        gk<0,true,1><<<g1(gN), 256, SMEM_BYTES>>>(sg, hhi, hlo, nullptr, nullptr,
            nullptr, nullptr, nullptr, nullptr, nullptr, nullptr, N, gN);
    }
    dec2_kernel<<<(N + 63) / 64, 128>>>(f1, dec_W2, dec_b2, dec_W3, dec_b3,
                                        bc_disp, bc_rot, face_mask, (float*)d_out, N);
}

// round 15
// speedup vs baseline: 1.0680x; 1.0680x over previous
#include <cuda_runtime.h>
#include <cuda_bf16.h>
#include <cstdint>

// ===========================================================================
// PIGNN forward — mma.sync bf16 hi/lo split GEMMs, persistent-B in smem.
// Base: proven 3934.7us kernel. Delta: edge-encoder GEMM folded away:
//   e@mW3 == t@(encW2@mW3) + b_e@mW3   (e linear in t = relu(ea@W1+b1))
// msg GEMM reads t (thi/tlo) with fused weights; gk kernel unchanged.
// ===========================================================================

#define NN_MAX 100000
#define NE_MAX 600000

__device__ float g_h   [(size_t)NN_MAX * 128];
__device__ float g_agg [(size_t)NN_MAX * 128];
__device__ float g_f1  [(size_t)NN_MAX * 128];   // U1 during layers, f1 in decoder
__device__ float g_p1  [(size_t)NN_MAX * 128];
__device__ float g_p2  [(size_t)NN_MAX * 128];
__device__ __nv_bfloat16 g_hhi[(size_t)NN_MAX * 128];
__device__ __nv_bfloat16 g_hlo[(size_t)NN_MAX * 128];
__device__ __nv_bfloat16 g_ghi[(size_t)NE_MAX * 128];   // agg-split target
__device__ __nv_bfloat16 g_glo[(size_t)NE_MAX * 128];
__device__ __nv_bfloat16 g_thi[(size_t)NE_MAX * 128];   // node-mlp1 transient, then t
__device__ __nv_bfloat16 g_tlo[(size_t)NE_MAX * 128];
#define W128_CNT 21
#define WUPD_OFF (W128_CNT * 16384)
#define WTOT (WUPD_OFF + 6 * 32768)
__device__ __nv_bfloat16 g_whi[WTOT];
__device__ __nv_bfloat16 g_wlo[WTOT];
__device__ float g_zbias[128];    // zero-initialized, never written
__device__ float g_msgb[6 * 128]; // fused msg bias: msg_b + b_e@mW3

// ---------------------------------------------------------------------------
__device__ __forceinline__ uint32_t smem_to_u32(const void* p) {
    uint32_t a;
    asm("{ .reg .u64 t; cvta.to.shared.u64 t, %1; cvt.u32.u64 %0, t; }" : "=r"(a) : "l"(p));
    return a;
}
__device__ __forceinline__ void ldmx4(uint32_t& r0, uint32_t& r1, uint32_t& r2, uint32_t& r3,
                                      uint32_t addr) {
    asm volatile("ldmatrix.sync.aligned.m8n8.x4.shared.b16 {%0,%1,%2,%3}, [%4];"
                 : "=r"(r0), "=r"(r1), "=r"(r2), "=r"(r3) : "r"(addr));
}
__device__ __forceinline__ void mma_bf16(float& c0, float& c1, float& c2, float& c3,
                                         uint32_t a0, uint32_t a1, uint32_t a2, uint32_t a3,
                                         uint32_t b0, uint32_t b1) {
    asm volatile("mma.sync.aligned.m16n8k16.row.col.f32.bf16.bf16.f32 "
                 "{%0,%1,%2,%3}, {%4,%5,%6,%7}, {%8,%9}, {%0,%1,%2,%3};"
                 : "+f"(c0), "+f"(c1), "+f"(c2), "+f"(c3)
                 : "r"(a0), "r"(a1), "r"(a2), "r"(a3), "r"(b0), "r"(b1));
}
__device__ __forceinline__ void cpa16(uint32_t saddr, const void* g) {
    asm volatile("cp.async.cg.shared.global [%0], [%1], 16;" :: "r"(saddr), "l"(g));
}
#define CP_COMMIT() asm volatile("cp.async.commit_group;" ::: "memory")
#define CP_WAIT1()  asm volatile("cp.async.wait_group 1;" ::: "memory")
#define CP_WAIT0()  asm volatile("cp.async.wait_group 0;" ::: "memory")
__device__ __forceinline__ void red_add_v2(float* addr, float a, float b) {
    asm volatile("red.global.add.v2.f32 [%0], {%1,%2};"
                 :: "l"(addr), "f"(a), "f"(b) : "memory");
}
__device__ __forceinline__ uint32_t pack_bf2(float a, float b) {
    __nv_bfloat162 v = __floats2bfloat162_rn(a, b);
    return *reinterpret_cast<uint32_t*>(&v);
}
__device__ __forceinline__ void split2(float a, float b, uint32_t& hp, uint32_t& lp) {
    __nv_bfloat16 ha = __float2bfloat16(a), hb = __float2bfloat16(b);
    float la = a - __bfloat162float(ha), lb = b - __bfloat162float(hb);
    __nv_bfloat162 hh = __nv_bfloat162(ha, hb);
    hp = *reinterpret_cast<uint32_t*>(&hh);
    lp = pack_bf2(la, lb);
}
__device__ __forceinline__ void split4(const float4 v, uint32_t& h01, uint32_t& h23,
                                       uint32_t& l01, uint32_t& l23) {
    split2(v.x, v.y, h01, l01);
    split2(v.z, v.w, h23, l23);
}

// ---------------------------------------------------------------------------
// SMEM: persistent B (hi 32K @0, lo 32K @32768; 4 slabs x 8K each) +
// 2 A stages @65536 (each: AHI 8K + ALO 8K = 16K). Total 96KB -> 2 CTAs/SM.
#define OFF_BLOP 32768
#define OFF_AST  65536
#define SMEM_BYTES (OFF_AST + 2 * 16384)
#define SWZ(row, chunk) ((uint32_t)(row) * 64 + ((uint32_t)((chunk) ^ (((row) >> 1) & 3)) << 4))

struct Seg { const __nv_bfloat16* bhi; const __nv_bfloat16* blo;
             const float* bias; float* cout; int ldb; };
struct Segs { Seg s[3]; };

// ---------------------------------------------------------------------------
// GEMM: tile 128x128, K=128 (4 slabs of 32), 3-pass bf16 split, 256 thr,
// persistent B, persistent CTAs, 2-stage A pipeline (proven R8 structure).
// EPI: 0 store fp32 (RELU opt) | 1 store split | 3 msg RED | 4 fp32+split
//      5 upd2: o=relu(U1+acc+b); cout+=o; split cout
// NSEG: static CTA partition over up to 3 (B, bias, cout) segments.
template<int EPI, bool RELU, int NSEG>
__global__ __launch_bounds__(256, 2)
void gk(Segs segs,
        const __nv_bfloat16* __restrict__ Ahi, const __nv_bfloat16* __restrict__ Alo,
        __nv_bfloat16* __restrict__ OutHi, __nv_bfloat16* __restrict__ OutLo,
        const int* __restrict__ src, const int* __restrict__ dst,
        const float* __restrict__ P1, const float* __restrict__ P2,
        float* __restrict__ AGGZ, const float* __restrict__ U1,
        int M, int ntiles)
{
    extern __shared__ char smem[];
    const uint32_t sb = smem_to_u32(smem);
    const int t = threadIdx.x;
    const int lane = t & 31;
    const int wid = t >> 5;
    const int wm = wid & 3;
    const int wn = wid >> 2;

    const int seg  = (NSEG == 1) ? 0 : (blockIdx.x % NSEG);
    const int nbSeg = gridDim.x / NSEG;
    const int bidS = (NSEG == 1) ? blockIdx.x : (blockIdx.x / NSEG);
    const Seg sg = segs.s[seg];

    const int ntl = (bidS < ntiles) ? ((ntiles - 1 - bidS) / nbSeg + 1) : 0;
    const int L = ntl * 4;
    if (L == 0) return;

    const int c2 = (lane & 3) * 2;
    float2 bw[8];
#pragma unroll
    for (int jn = 0; jn < 8; ++jn)
        bw[jn] = *reinterpret_cast<const float2*>(&sg.bias[wn * 64 + jn * 8 + c2]);

    // ---- persistent B load (4 slabs, hi+lo) ----
#pragma unroll
    for (int i = 0; i < 8; ++i) {
        int id = t + i * 256;            // 0..2047
        int slab = id >> 9;
        int row = (id >> 2) & 127;
        int c = id & 3;
        uint32_t off = (uint32_t)slab * 8192 + SWZ(row, c);
        size_t gix = (size_t)row * sg.ldb + slab * 32 + c * 8;
        cpa16(sb + off, sg.bhi + gix);
        cpa16(sb + OFF_BLOP + off, sg.blo + gix);
    }
    CP_COMMIT();

    auto fillA = [&](int l) {
        int tl = l >> 2;
        int s = l & 3;
        int m0f = (bidS + tl * nbSeg) * 128;
        int kb = s << 5;
        uint32_t buf = sb + OFF_AST + (uint32_t)(l & 1) * 16384;
#pragma unroll
        for (int i = 0; i < 2; ++i) {
            int id = t + i * 256;
            int row = id >> 2;
            int c = id & 3;
            int m = m0f + row;
            int mc = m < M ? m : M - 1;
            uint32_t off = SWZ(row, c);
            cpa16(buf + off, Ahi + (size_t)mc * 128 + kb + c * 8);
            cpa16(buf + 8192 + off, Alo + (size_t)mc * 128 + kb + c * 8);
        }
        CP_COMMIT();
    };

    fillA(0);

    float acc[2][8][4];
#pragma unroll
    for (int i = 0; i < 2; ++i)
#pragma unroll
        for (int j = 0; j < 8; ++j)
#pragma unroll
            for (int r = 0; r < 4; ++r) acc[i][j][r] = 0.f;

    int tl_cur = 0;
    for (int l = 0; l < L; ++l) {
        __syncthreads();                       // prior readers of next stage done
        if (l + 1 < L) { fillA(l + 1); CP_WAIT1(); }
        else CP_WAIT0();
        __syncthreads();                       // fills visible
        const uint32_t bufA = sb + OFF_AST + (uint32_t)(l & 1) * 16384;
        const uint32_t bufB = sb + (uint32_t)(l & 3) * 8192;
#pragma unroll
        for (int ks = 0; ks < 2; ++ks) {
            uint32_t ahi[2][4], alo[2][4];
            uint32_t ca = ks * 2 + (lane >> 4);
            uint32_t arow = wm * 32 + (lane & 15);
#pragma unroll
            for (int i = 0; i < 2; ++i) {
                uint32_t r = arow + i * 16;
                uint32_t off = SWZ(r, ca);
                ldmx4(ahi[i][0], ahi[i][1], ahi[i][2], ahi[i][3], bufA + off);
                ldmx4(alo[i][0], alo[i][1], alo[i][2], alo[i][3], bufA + 8192 + off);
            }
            uint32_t nr = wn * 64 + (lane & 7) + (lane >> 4) * 8;
            uint32_t cbk = ks * 2 + ((lane >> 3) & 1);
#pragma unroll
            for (int j2 = 0; j2 < 4; ++j2) {
                uint32_t r = nr + j2 * 16;
                uint32_t off = SWZ(r, cbk);
                uint32_t bh[4], bl[4];
                ldmx4(bh[0], bh[1], bh[2], bh[3], bufB + off);
                ldmx4(bl[0], bl[1], bl[2], bl[3], bufB + OFF_BLOP + off);
#pragma unroll
                for (int i = 0; i < 2; ++i) {
#pragma unroll
                    for (int jj = 0; jj < 2; ++jj) {
                        float* c = acc[i][j2 * 2 + jj];
                        mma_bf16(c[0], c[1], c[2], c[3],
                                 ahi[i][0], ahi[i][1], ahi[i][2], ahi[i][3],
                                 bh[jj * 2], bh[jj * 2 + 1]);
                        mma_bf16(c[0], c[1], c[2], c[3],
                                 alo[i][0], alo[i][1], alo[i][2], alo[i][3],
                                 bh[jj * 2], bh[jj * 2 + 1]);
                        mma_bf16(c[0], c[1], c[2], c[3],
                                 ahi[i][0], ahi[i][1], ahi[i][2], ahi[i][3],
                                 bl[jj * 2], bl[jj * 2 + 1]);
                    }
                }
            }
        }

        if ((l & 3) == 3) {
            // ---- register-direct epilogue for tile tl_cur ----
            const int m0 = (bidS + tl_cur * nbSeg) * 128;
            ++tl_cur;
            float* co = sg.cout;
#pragma unroll
            for (int i = 0; i < 2; ++i) {
                const int ra = m0 + wm * 32 + i * 16 + (lane >> 2);
                const int rb = ra + 8;
                const bool va = ra < M, vb = rb < M;
                int sA = 0, dA = 0, sB = 0, dB = 0;
                if (EPI == 3) {
                    if (va) { sA = __ldg(&src[ra]); dA = __ldg(&dst[ra]); }
                    if (vb) { sB = __ldg(&src[rb]); dB = __ldg(&dst[rb]); }
                }
#pragma unroll
                for (int jn = 0; jn < 8; ++jn) {
                    float* c = acc[i][jn];
                    const int col = wn * 64 + jn * 8 + c2;
                    float v0 = c[0] + bw[jn].x, v1 = c[1] + bw[jn].y;
                    float v2 = c[2] + bw[jn].x, v3 = c[3] + bw[jn].y;
                    c[0] = c[1] = c[2] = c[3] = 0.f;
                    if (EPI == 0 || EPI == 4) {
                        if (RELU) { v0 = fmaxf(v0, 0.f); v1 = fmaxf(v1, 0.f);
                                    v2 = fmaxf(v2, 0.f); v3 = fmaxf(v3, 0.f); }
                        if (va) *reinterpret_cast<float2*>(&co[(size_t)ra * 128 + col]) =
                            make_float2(v0, v1);
                        if (vb) *reinterpret_cast<float2*>(&co[(size_t)rb * 128 + col]) =
                            make_float2(v2, v3);
                        if (EPI == 4) {
                            uint32_t hp, lp;
                            if (va) {
                                split2(v0, v1, hp, lp);
                                *reinterpret_cast<uint32_t*>(OutHi + (size_t)ra * 128 + col) = hp;
                                *reinterpret_cast<uint32_t*>(OutLo + (size_t)ra * 128 + col) = lp;
                            }
                            if (vb) {
                                split2(v2, v3, hp, lp);
                                *reinterpret_cast<uint32_t*>(OutHi + (size_t)rb * 128 + col) = hp;
                                *reinterpret_cast<uint32_t*>(OutLo + (size_t)rb * 128 + col) = lp;
                            }
                        }
                    } else if (EPI == 1) {
                        uint32_t hp, lp;
                        if (va) {
                            split2(v0, v1, hp, lp);
                            *reinterpret_cast<uint32_t*>(OutHi + (size_t)ra * 128 + col) = hp;
                            *reinterpret_cast<uint32_t*>(OutLo + (size_t)ra * 128 + col) = lp;
                        }
                        if (vb) {
                            split2(v2, v3, hp, lp);
                            *reinterpret_cast<uint32_t*>(OutHi + (size_t)rb * 128 + col) = hp;
                            *reinterpret_cast<uint32_t*>(OutLo + (size_t)rb * 128 + col) = lp;
                        }
                    } else if (EPI == 5) {
                        uint32_t hp, lp;
                        if (va) {
                            float2 u = __ldg(reinterpret_cast<const float2*>(
                                                 &U1[(size_t)ra * 128 + col]));
                            float2 o = *reinterpret_cast<float2*>(&co[(size_t)ra * 128 + col]);
                            o.x += fmaxf(v0 + u.x, 0.f);
                            o.y += fmaxf(v1 + u.y, 0.f);
                            *reinterpret_cast<float2*>(&co[(size_t)ra * 128 + col]) = o;
                            split2(o.x, o.y, hp, lp);
                            *reinterpret_cast<uint32_t*>(OutHi + (size_t)ra * 128 + col) = hp;
                            *reinterpret_cast<uint32_t*>(OutLo + (size_t)ra * 128 + col) = lp;
                        }
                        if (vb) {
                            float2 u = __ldg(reinterpret_cast<const float2*>(
                                                 &U1[(size_t)rb * 128 + col]));
                            float2 o = *reinterpret_cast<float2*>(&co[(size_t)rb * 128 + col]);
                            o.x += fmaxf(v2 + u.x, 0.f);
                            o.y += fmaxf(v3 + u.y, 0.f);
                            *reinterpret_cast<float2*>(&co[(size_t)rb * 128 + col]) = o;
                            split2(o.x, o.y, hp, lp);
                            *reinterpret_cast<uint32_t*>(OutHi + (size_t)rb * 128 + col) = hp;
                            *reinterpret_cast<uint32_t*>(OutLo + (size_t)rb * 128 + col) = lp;
                        }
                    } else {  // EPI 3
                        if (va) {
                            float2 a1 = __ldg(reinterpret_cast<const float2*>(
                                                  &P1[(size_t)sA * 128 + col]));
                            float2 a2 = __ldg(reinterpret_cast<const float2*>(
                                                  &P2[(size_t)dA * 128 + col]));
                            float x0 = fmaxf(v0 + a1.x + a2.x, 0.f);
                            float x1 = fmaxf(v1 + a1.y + a2.y, 0.f);
                            red_add_v2(&AGGZ[(size_t)dA * 128 + col], x0, x1);
                        }
                        if (vb) {
                            float2 a1 = __ldg(reinterpret_cast<const float2*>(
                                                  &P1[(size_t)sB * 128 + col]));
                            float2 a2 = __ldg(reinterpret_cast<const float2*>(
                                                  &P2[(size_t)dB * 128 + col]));
                            float x2 = fmaxf(v2 + a1.x + a2.x, 0.f);
                            float x3 = fmaxf(v3 + a1.y + a2.y, 0.f);
                            red_add_v2(&AGGZ[(size_t)dB * 128 + col], x2, x3);
                        }
                    }
                }
            }
        }
    }
}

// ---------------------------------------------------------------------------
// split agg (fp32) -> bf16 hi/lo, and zero agg for the next layer
__global__ void splitagg(float* __restrict__ agg, __nv_bfloat16* __restrict__ hi,
                         __nv_bfloat16* __restrict__ lo, int n4) {
    int i = blockIdx.x * blockDim.x + threadIdx.x;
    if (i >= n4) return;
    float4 v = reinterpret_cast<float4*>(agg)[i];
    uint32_t h01, h23, l01, l23;
    split4(v, h01, h23, l01, l23);
    reinterpret_cast<uint2*>(hi)[i] = make_uint2(h01, h23);
    reinterpret_cast<uint2*>(lo)[i] = make_uint2(l01, l23);
    reinterpret_cast<float4*>(agg)[i] = make_float4(0.f, 0.f, 0.f, 0.f);
}

// ---------------------------------------------------------------------------
struct PtrTab { const float* p[W128_CNT]; };

__global__ void prep_w128(PtrTab tab, __nv_bfloat16* __restrict__ hi, __nv_bfloat16* __restrict__ lo) {
    int mat = blockIdx.y;
    int i = blockIdx.x * 256 + threadIdx.x;
    if (i >= 16384) return;
    int n = i >> 7, k = i & 127;
    float w = tab.p[mat][k * 128 + n];
    __nv_bfloat16 h = __float2bfloat16(w);
    hi[(size_t)mat * 16384 + i] = h;
    lo[(size_t)mat * 16384 + i] = __float2bfloat16(w - __bfloat162float(h));
}
__global__ void prep_w256(const float* __restrict__ W, __nv_bfloat16* __restrict__ hi,
                          __nv_bfloat16* __restrict__ lo) {
    int mat = blockIdx.y;
    int i = blockIdx.x * 256 + threadIdx.x;
    if (i >= 32768) return;
    int n = i >> 8, k = i & 255;
    float w = W[(size_t)mat * 256 * 128 + k * 128 + n];
    __nv_bfloat16 h = __float2bfloat16(w);
    hi[(size_t)(WUPD_OFF + mat * 32768) + i] = h;
    lo[(size_t)(WUPD_OFF + mat * 32768) + i] = __float2bfloat16(w - __bfloat162float(h));
}

// fused msg weight: W'_l = encW2 @ mW3_l, stored transposed+split at slot 3+l*3+2
// (overwrites the plain mW3 slot written by prep_w128 — launched after it).
__global__ void prep_fuse(const float* __restrict__ encW2, const float* __restrict__ msg_W,
                          __nv_bfloat16* __restrict__ hi, __nv_bfloat16* __restrict__ lo) {
    int l = blockIdx.y;
    int i = blockIdx.x * 256 + threadIdx.x;
    if (i >= 16384) return;
    int n = i >> 7, k = i & 127;
    const float* mW3 = msg_W + (size_t)l * 49152 + 32768;  // rows 256..383 of mW_l
    float acc = 0.f;
#pragma unroll 4
    for (int c = 0; c < 128; ++c)
        acc += encW2[k * 128 + c] * mW3[c * 128 + n];
    int slot = 3 + l * 3 + 2;
    __nv_bfloat16 h = __float2bfloat16(acc);
    hi[(size_t)slot * 16384 + i] = h;
    lo[(size_t)slot * 16384 + i] = __float2bfloat16(acc - __bfloat162float(h));
}
// fused msg bias: msgb_l = msg_b_l + b_e @ mW3_l
__global__ void prep_mbias(const float* __restrict__ msg_b, const float* __restrict__ e_b2,
                           const float* __restrict__ msg_W, float* __restrict__ out) {
    int l = blockIdx.x;
    int n = threadIdx.x;
    const float* mW3 = msg_W + (size_t)l * 49152 + 32768;
    float acc = msg_b[l * 128 + n];
    for (int c = 0; c < 128; ++c) acc += e_b2[c] * mW3[c * 128 + n];
    out[l * 128 + n] = acc;
}

__global__ void zero_kernel(float* __restrict__ p, int n4) {
    int i = blockIdx.x * blockDim.x + threadIdx.x;
    if (i < n4) reinterpret_cast<float4*>(p)[i] = make_float4(0.f, 0.f, 0.f, 0.f);
}

// batched tiny-K first linear + relu, writes pre-split bf16 hi/lo
__global__ void mlp1_kernel(const float* __restrict__ X, const float* __restrict__ W,
                            const float* __restrict__ b,
                            __nv_bfloat16* __restrict__ outHi, __nv_bfloat16* __restrict__ outLo,
                            int K, int M)
{
    __shared__ float Ws[10 * 128];
    __shared__ float Xs[32 * 10];
    __shared__ float bs[128];
    int t = threadIdx.x;  // 128
    for (int i = t; i < K * 128; i += 128) Ws[i] = W[i];
    bs[t] = b[t];
    int r0 = blockIdx.x * 32;
    int nrow = min(32, M - r0);
    for (int i = t; i < nrow * K; i += 128) Xs[i] = X[(size_t)r0 * K + i];
    __syncthreads();
    for (int r = 0; r < nrow; ++r) {
        float acc = bs[t];
        for (int k = 0; k < K; ++k) acc += Xs[r * K + k] * Ws[k * 128 + t];
        acc = fmaxf(acc, 0.f);
        __nv_bfloat16 hv = __float2bfloat16(acc);
        outHi[(size_t)(r0 + r) * 128 + t] = hv;
        outLo[(size_t)(r0 + r) * 128 + t] = __float2bfloat16(acc - __bfloat162float(hv));
    }
}

// fused decoder tail
__global__ void dec2_kernel(const float* __restrict__ f1, const float* __restrict__ W2,
                            const float* __restrict__ b2, const float* __restrict__ W3,
                            const float* __restrict__ b3, const float* __restrict__ bc_disp,
                            const float* __restrict__ bc_rot, const float* __restrict__ face_mask,
                            float* __restrict__ out, int N)
{
    __shared__ float W2s[128 * 64];
    __shared__ float W3s[64 * 15];
    __shared__ float b2s[64], b3s[16];
    __shared__ float f1s[2][128];
    __shared__ float f2s[2][64];

    int t = threadIdx.x;
    for (int i = t; i < 128 * 64; i += 128) W2s[i] = W2[i];
    for (int i = t; i < 64 * 15;  i += 128) W3s[i] = W3[i];
    if (t < 64) b2s[t] = b2[t];
    if (t < 15) b3s[t] = b3[t];
    __syncthreads();

    int base = blockIdx.x * 64;
    for (int it = 0; it < 32; ++it) {
        int n0 = base + it * 2;
#pragma unroll
        for (int r = 0; r < 2; ++r) {
            int n = n0 + r;
            f1s[r][t] = (n < N) ? f1[(size_t)n * 128 + t] : 0.f;
        }
        __syncthreads();
        {
            int rn = t >> 6, j = t & 63;
            float acc = b2s[j];
#pragma unroll 8
            for (int k = 0; k < 128; ++k) acc += f1s[rn][k] * W2s[k * 64 + j];
            f2s[rn][j] = fmaxf(acc, 0.f);
        }
        __syncthreads();
        if (t < 30) {
            int rr = t / 15, c = t % 15;
            int n = n0 + rr;
            if (n < N) {
                float acc = b3s[c];
#pragma unroll 8
                for (int k = 0; k < 64; ++k) acc += f2s[rr][k] * W3s[k * 15 + c];
                float mask;
                if (c < 2)       mask = 1.f - bc_disp[n];
                else if (c == 2) mask = 1.f - bc_rot[n];
                else             mask = face_mask[(size_t)n * 4 + (c - 3) / 3];
                out[(size_t)n * 15 + c] = acc * mask;
            }
        }
        __syncthreads();
    }
}

// ---------------------------------------------------------------------------
extern "C" void kernel_launch(void* const* d_in, const int* in_sizes, int n_in,
                              void* d_out, int out_size)
{
    const float* x         = (const float*)d_in[0];
    const float* edge_attr = (const float*)d_in[1];
    const int*   edge_idx  = (const int*)  d_in[2];
    const float* bc_disp   = (const float*)d_in[3];
    const float* bc_rot    = (const float*)d_in[4];
    const float* face_mask = (const float*)d_in[5];
    const float* enc_n_W1  = (const float*)d_in[6];
    const float* enc_n_b1  = (const float*)d_in[7];
    const float* enc_n_W2  = (const float*)d_in[8];
    const float* enc_n_b2  = (const float*)d_in[9];
    const float* enc_e_W1  = (const float*)d_in[10];
    const float* enc_e_b1  = (const float*)d_in[11];
    const float* enc_e_W2  = (const float*)d_in[12];
    const float* enc_e_b2  = (const float*)d_in[13];
    const float* msg_W     = (const float*)d_in[14];
    const float* msg_b     = (const float*)d_in[15];
    const float* upd_W     = (const float*)d_in[16];
    const float* upd_b     = (const float*)d_in[17];
    const float* dec_W1    = (const float*)d_in[18];
    const float* dec_b1    = (const float*)d_in[19];
    const float* dec_W2    = (const float*)d_in[20];
    const float* dec_b2    = (const float*)d_in[21];
    const float* dec_W3    = (const float*)d_in[22];
    const float* dec_b3    = (const float*)d_in[23];

    const int N = in_sizes[0] / 9;
    const int E = in_sizes[1] / 10;
    const int* src = edge_idx;
    const int* dst = edge_idx + E;

    float *h, *agg, *f1, *p1, *p2, *zb, *mb;
    __nv_bfloat16 *hhi, *hlo, *ghi, *glo, *thi, *tlo, *whi, *wlo;
    cudaGetSymbolAddress((void**)&h,   g_h);
    cudaGetSymbolAddress((void**)&agg, g_agg);
    cudaGetSymbolAddress((void**)&f1,  g_f1);
    cudaGetSymbolAddress((void**)&p1,  g_p1);
    cudaGetSymbolAddress((void**)&p2,  g_p2);
    cudaGetSymbolAddress((void**)&zb,  g_zbias);
    cudaGetSymbolAddress((void**)&mb,  g_msgb);
    cudaGetSymbolAddress((void**)&hhi, g_hhi);
    cudaGetSymbolAddress((void**)&hlo, g_hlo);
    cudaGetSymbolAddress((void**)&ghi, g_ghi);
    cudaGetSymbolAddress((void**)&glo, g_glo);
    cudaGetSymbolAddress((void**)&thi, g_thi);
    cudaGetSymbolAddress((void**)&tlo, g_tlo);
    cudaGetSymbolAddress((void**)&whi, g_whi);
    cudaGetSymbolAddress((void**)&wlo, g_wlo);

    cudaFuncSetAttribute((const void*)gk<0,false,3>, cudaFuncAttributeMaxDynamicSharedMemorySize, SMEM_BYTES);
    cudaFuncSetAttribute((const void*)gk<3,true,1>,  cudaFuncAttributeMaxDynamicSharedMemorySize, SMEM_BYTES);
    cudaFuncSetAttribute((const void*)gk<5,true,1>,  cudaFuncAttributeMaxDynamicSharedMemorySize, SMEM_BYTES);
    cudaFuncSetAttribute((const void*)gk<4,false,1>, cudaFuncAttributeMaxDynamicSharedMemorySize, SMEM_BYTES);
    cudaFuncSetAttribute((const void*)gk<0,true,1>,  cudaFuncAttributeMaxDynamicSharedMemorySize, SMEM_BYTES);

    // ---- weight prep ----
    PtrTab tab;
    tab.p[0] = enc_n_W2;
    tab.p[1] = enc_e_W2;
    tab.p[2] = dec_W1;
    for (int l = 0; l < 6; ++l)
        for (int j = 0; j < 3; ++j)
            tab.p[3 + l * 3 + j] = msg_W + (size_t)l * 384 * 128 + (size_t)j * 128 * 128;
    prep_w128<<<dim3(64, W128_CNT), 256>>>(tab, whi, wlo);
    prep_w256<<<dim3(128, 6), 256>>>(upd_W, whi, wlo);
    prep_fuse<<<dim3(64, 6), 256>>>(enc_e_W2, msg_W, whi, wlo);  // overwrites mW3 slots
    prep_mbias<<<6, 128>>>(msg_b, enc_e_b2, msg_W, mb);

    const int gN = (N + 127) / 128;
    const int gE = (E + 127) / 128;
    auto WH = [&](int j) { return whi + (size_t)j * 16384; };
    auto WL = [&](int j) { return wlo + (size_t)j * 16384; };
    auto mkseg = [](const __nv_bfloat16* bh, const __nv_bfloat16* bl,
                    const float* bi, float* co, int ldb) {
        Seg s; s.bhi = bh; s.blo = bl; s.bias = bi; s.cout = co; s.ldb = ldb; return s;
    };

    const int PG1 = 296;                   // NSEG=1 grid
    const int PG3 = 294;                   // NSEG=3 grid (divisible by 3)
    auto g1 = [&](int nt) { return nt < PG1 ? nt : PG1; };

    // ---- node encoder (thi/tlo used transiently) ----
    mlp1_kernel<<<(N + 31) / 32, 128>>>(x, enc_n_W1, enc_n_b1, thi, tlo, 9, N);
    {
        Segs sg; sg.s[0] = mkseg(WH(0), WL(0), enc_n_b2, h, 128);
        gk<4,false,1><<<g1(gN), 256, SMEM_BYTES>>>(sg, thi, tlo, hhi, hlo,
            nullptr, nullptr, nullptr, nullptr, nullptr, nullptr, N, gN);
    }
    // ---- edge hidden state t -> thi/tlo (persists all layers; e never built) ----
    mlp1_kernel<<<(E + 31) / 32, 128>>>(edge_attr, enc_e_W1, enc_e_b1, thi, tlo, 10, E);

    zero_kernel<<<(N * 128 / 4 + 255) / 256, 256>>>(agg, N * 128 / 4);

    // ---- message-passing layers ----
    for (int l = 0; l < 6; ++l) {
        int j = 3 + l * 3;
        const __nv_bfloat16* uh = whi + WUPD_OFF + (size_t)l * 32768;
        const __nv_bfloat16* ul = wlo + WUPD_OFF + (size_t)l * 32768;
        {   // P1 = h@mW1, P2 = h@mW2, U1 = h@uW1 (3 segments)
            Segs sg;
            sg.s[0] = mkseg(WH(j),   WL(j),   zb, p1, 128);
            sg.s[1] = mkseg(WH(j+1), WL(j+1), zb, p2, 128);
            sg.s[2] = mkseg(uh, ul, zb, f1, 256);
            int grid = (3 * gN < PG3) ? 3 * gN : PG3;
            gk<0,false,3><<<grid, 256, SMEM_BYTES>>>(sg, hhi, hlo, nullptr, nullptr,
                nullptr, nullptr, nullptr, nullptr, nullptr, nullptr, N, gN);
        }
        {   // msg: acc = t@W'_l; epi relu(acc + mb + P1[src] + P2[dst]) RED->agg[dst]
            Segs sg; sg.s[0] = mkseg(WH(j+2), WL(j+2), mb + l * 128, nullptr, 128);
            gk<3,true,1><<<g1(gE), 256, SMEM_BYTES>>>(sg, thi, tlo, nullptr, nullptr,
                src, dst, p1, p2, agg, nullptr, E, gE);
        }
        // agg -> bf16 hi/lo (ghi/glo), zero agg
        splitagg<<<(N * 32 + 255) / 256, 256>>>(agg, ghi, glo, N * 32);
        {   // upd2: o = relu(U1 + agg@uW2 + ub); h += o; split h
            Segs sg; sg.s[0] = mkseg(uh + 128, ul + 128, upd_b + l * 128, h, 256);
            gk<5,true,1><<<g1(gN), 256, SMEM_BYTES>>>(sg, ghi, glo, hhi, hlo,
                nullptr, nullptr, nullptr, nullptr, nullptr, f1, N, gN);
        }
    }

    // ---- decoder ----
    {
        Segs sg; sg.s[0] = mkseg(WH(2), WL(2), dec_b1, f1, 128);
        gk<0,true,1><<<g1(gN), 256, SMEM_BYTES>>>(sg, hhi, hlo, nullptr, nullptr,
            nullptr, nullptr, nullptr, nullptr, nullptr, nullptr, N, gN);
    }
    dec2_kernel<<<(N + 63) / 64, 128>>>(f1, dec_W2, dec_b2, dec_W3, dec_b3,
                                        bc_disp, bc_rot, face_mask, (float*)d_out, N);
}